// round 2
// baseline (speedup 1.0000x reference)
#include <cuda_runtime.h>
#include <cstdint>

// Submanifold sparse conv, sparsity-exploiting warp-per-site kernel.
// features [N,32] f32, weight [27,32,32] f32, bias [32] f32,
// nbr_idx [N,27] i32, nbr_mask [N,27] i32 (bool materialized as int32),
// out [N,32] f32.

#define C 32
#define KTAPS 27
#define WARPS_PER_BLOCK 8
#define THREADS (WARPS_PER_BLOCK * 32)
#define NBLOCKS 296   // 2 per SM on 148 SMs

// smem: weights 27*32*32 floats, then per-warp feature row staging
#define W_FLOATS (KTAPS * C * C)          // 27648
#define SMEM_BYTES (W_FLOATS * 4 + WARPS_PER_BLOCK * C * 4)

__global__ void __launch_bounds__(THREADS, 2)
subm_conv_kernel(const float* __restrict__ features,
                 const float* __restrict__ weight,
                 const float* __restrict__ bias,
                 const int*   __restrict__ nbr_idx,
                 const int*   __restrict__ nbr_mask,
                 float* __restrict__ out,
                 int n_sites)
{
    extern __shared__ float smem[];
    float* ws = smem;                                  // [27][32][32]
    float* sf = smem + W_FLOATS;                       // [WARPS][32]

    const int tid  = threadIdx.x;
    const int lane = tid & 31;
    const int wib  = tid >> 5;                         // warp in block

    // Stage all weights into shared (vectorized). 27648 floats = 6912 float4.
    {
        const float4* wsrc = reinterpret_cast<const float4*>(weight);
        float4* wdst = reinterpret_cast<float4*>(ws);
        #pragma unroll
        for (int i = tid; i < W_FLOATS / 4; i += THREADS)
            wdst[i] = wsrc[i];
    }
    __syncthreads();

    const float my_bias = bias[lane];
    float* myrow = sf + wib * C;

    const int gwarp  = blockIdx.x * WARPS_PER_BLOCK + wib;
    const int nwarps = gridDim.x * WARPS_PER_BLOCK;

    for (int site = gwarp; site < n_sites; site += nwarps) {
        // lanes 0..26 fetch idx + mask for the 27 taps
        int   my_idx = 0;
        bool  my_ok  = false;
        if (lane < KTAPS) {
            my_idx = nbr_idx[site * KTAPS + lane];
            my_ok  = (nbr_mask[site * KTAPS + lane] != 0);
        }
        unsigned active = __ballot_sync(0xffffffffu, my_ok);

        float acc = my_bias;

        while (active) {
            const int k = __ffs(active) - 1;
            active &= active - 1;
            const int nb = __shfl_sync(0xffffffffu, my_idx, k);

            // coalesced 128B gather of the neighbor feature row
            myrow[lane] = features[nb * C + lane];
            __syncwarp();

            const float* wk = ws + k * (C * C);
            #pragma unroll
            for (int c4 = 0; c4 < C; c4 += 4) {
                // uniform-address broadcast LDS.128
                const float4 fv = *reinterpret_cast<const float4*>(myrow + c4);
                acc += fv.x * wk[(c4 + 0) * C + lane];
                acc += fv.y * wk[(c4 + 1) * C + lane];
                acc += fv.z * wk[(c4 + 2) * C + lane];
                acc += fv.w * wk[(c4 + 3) * C + lane];
            }
            __syncwarp();
        }

        out[site * C + lane] = acc;
    }
}

extern "C" void kernel_launch(void* const* d_in, const int* in_sizes, int n_in,
                              void* d_out, int out_size)
{
    const float* features = (const float*)d_in[0];
    const float* weight   = (const float*)d_in[1];
    const float* bias     = (const float*)d_in[2];
    const int*   nbr_idx  = (const int*)d_in[3];
    const int*   nbr_mask = (const int*)d_in[4];
    float*       out      = (float*)d_out;

    const int n_sites = in_sizes[0] / C;

    static bool attr_set = false;
    if (!attr_set) {
        cudaFuncSetAttribute(subm_conv_kernel,
                             cudaFuncAttributeMaxDynamicSharedMemorySize,
                             SMEM_BYTES);
        attr_set = true;
    }

    subm_conv_kernel<<<NBLOCKS, THREADS, SMEM_BYTES>>>(
        features, weight, bias, nbr_idx, nbr_mask, out, n_sites);
}